// round 2
// baseline (speedup 1.0000x reference)
#include <cuda_runtime.h>
#include <cuda_bf16.h>

// PaletteBoundLoss: scalar loss over 1M points vs a fixed octahedron hull.
//   loss = W_IN * mean_{inside}(d2 to nearest vertex) + W_OUT * max_{outside}(d2 to surface)
// Octant-folded: q=|p| reduces 8 faces -> 1 plane test, 6 verts -> closed form,
// 8 triangles -> 1 closest-point-on-triangle vs (e_x,e_y,e_z).

#define NBLK 1036              // 7 * 148 SMs
#define NTHR 256
#define NWARP (NTHR / 32)
#define PB_TOL 1e-8f

__device__ float        g_psum[NBLK];
__device__ int          g_pcnt[NBLK];
__device__ float        g_pmax[NBLK];
__device__ unsigned int g_ticket = 0;

__device__ __forceinline__ void eval_point(float x, float y, float z,
                                           float nc, float off,
                                           float& acc_sum, int& acc_cnt, float& acc_max)
{
    float qx = fabsf(x), qy = fabsf(y), qz = fabsf(z);
    float s = qx + qy + qz;
    bool inside = (s * nc - off) <= PB_TOL;

    // squared distance to nearest hull vertex (+-unit axis points)
    float qq  = fmaf(qx, qx, fmaf(qy, qy, qz * qz));
    float mx3 = fmaxf(qx, fmaxf(qy, qz));
    float d2v = qq + 1.0f - 2.0f * mx3;

    // closest point on triangle a=(1,0,0), b=(0,1,0), c=(0,0,1)
    // ab=(-1,1,0), ac=(-1,0,1); ab.ab=2, ab.ac=1, ac.ac=2
    float u  = 1.0f - qx;
    float d1 = u + qy;            // ab . (q-a)
    float d2 = u + qz;            // ac . (q-a)
    float d3 = d1 - 2.0f;         // ab . (q-b)
    float d4 = d2 - 1.0f;         // ac . (q-b)
    float d5 = d1 - 1.0f;         // ab . (q-c)
    float d6 = d2 - 2.0f;         // ac . (q-c)

    float vc = d1 * d4 - d3 * d2;
    float vb = d5 * d2 - d1 * d6;
    float va = d3 * d6 - d5 * d4;

    // interior (barycentric)
    float den = va + vb + vc;
    den = (fabsf(den) > 1e-20f) ? den : 1.0f;
    float inv = __fdividef(1.0f, den);
    float v = vb * inv, w = vc * inv;
    float rx = 1.0f - v - w, ry = v, rz = w;

    // edge bc
    float d43 = d4 - d3, d56 = d5 - d6;
    {
        float dd = d43 + d56; dd = (fabsf(dd) > 1e-20f) ? dd : 1.0f;
        float t = __fdividef(d43, dd);
        if ((va <= 0.0f) && (d43 >= 0.0f) && (d56 >= 0.0f)) { rx = 0.0f; ry = 1.0f - t; rz = t; }
    }
    // edge ac
    {
        float dd = d2 - d6; dd = (fabsf(dd) > 1e-20f) ? dd : 1.0f;
        float t = __fdividef(d2, dd);
        if ((vb <= 0.0f) && (d2 >= 0.0f) && (d6 <= 0.0f)) { rx = 1.0f - t; ry = 0.0f; rz = t; }
    }
    // edge ab
    {
        float dd = d1 - d3; dd = (fabsf(dd) > 1e-20f) ? dd : 1.0f;
        float t = __fdividef(d1, dd);
        if ((vc <= 0.0f) && (d1 >= 0.0f) && (d3 <= 0.0f)) { rx = 1.0f - t; ry = t; rz = 0.0f; }
    }
    // vertices c, b, a (reference override order: a wins last)
    if ((d6 >= 0.0f) && (d5 <= d6)) { rx = 0.0f; ry = 0.0f; rz = 1.0f; }
    if ((d3 >= 0.0f) && (d4 <= d3)) { rx = 0.0f; ry = 1.0f; rz = 0.0f; }
    if ((d1 <= 0.0f) && (d2 <= 0.0f)) { rx = 1.0f; ry = 0.0f; rz = 0.0f; }

    float dx = qx - rx, dy = qy - ry, dz = qz - rz;
    float sq = fmaf(dx, dx, fmaf(dy, dy, dz * dz));

    if (inside) { acc_sum += d2v; acc_cnt += 1; }
    else        { acc_max = fmaxf(acc_max, sq); }
}

// Full block reduction; results valid on thread 0. Uses caller-provided shared bufs.
__device__ __forceinline__ void block_reduce(float& rsum, int& rcnt, float& rmax,
                                             float* s_sum, int* s_cnt, float* s_max)
{
    #pragma unroll
    for (int o = 16; o > 0; o >>= 1) {
        rsum += __shfl_down_sync(0xffffffffu, rsum, o);
        rcnt += __shfl_down_sync(0xffffffffu, rcnt, o);
        rmax  = fmaxf(rmax, __shfl_down_sync(0xffffffffu, rmax, o));
    }
    int lane = threadIdx.x & 31, warp = threadIdx.x >> 5;
    if (lane == 0) { s_sum[warp] = rsum; s_cnt[warp] = rcnt; s_max[warp] = rmax; }
    __syncthreads();
    if (warp == 0) {
        rsum = (lane < NWARP) ? s_sum[lane] : 0.0f;
        rcnt = (lane < NWARP) ? s_cnt[lane] : 0;
        rmax = (lane < NWARP) ? s_max[lane] : 0.0f;
        #pragma unroll
        for (int o = NWARP / 2; o > 0; o >>= 1) {
            rsum += __shfl_down_sync(0xffffffffu, rsum, o);
            rcnt += __shfl_down_sync(0xffffffffu, rcnt, o);
            rmax  = fmaxf(rmax, __shfl_down_sync(0xffffffffu, rmax, o));
        }
    }
    __syncthreads();   // make shared bufs reusable afterwards
}

__global__ void __launch_bounds__(NTHR)
palette_loss_kernel(const float* __restrict__ pts,
                    const float* __restrict__ normals,
                    const float* __restrict__ offsets,
                    float* __restrict__ out, int npts)
{
    __shared__ float s_sum[NWARP];
    __shared__ int   s_cnt[NWARP];
    __shared__ float s_max[NWARP];
    __shared__ bool  s_last;

    const float nc  = fabsf(__ldg(normals));   // |n_x| of face 0 (all components equal magnitude)
    const float off = __ldg(offsets);          // face plane offset (all faces equal)

    float acc_sum = 0.0f; int acc_cnt = 0; float acc_max = 0.0f;

    const int ngroups = npts >> 2;             // 4 points per thread-iteration (3x float4)
    const float4* __restrict__ p4 = reinterpret_cast<const float4*>(pts);
    const int stride = gridDim.x * blockDim.x;
    const int tid0 = blockIdx.x * blockDim.x + threadIdx.x;
    for (int g = tid0; g < ngroups; g += stride) {
        float4 A = __ldg(&p4[3 * g + 0]);
        float4 B = __ldg(&p4[3 * g + 1]);
        float4 C = __ldg(&p4[3 * g + 2]);
        eval_point(A.x, A.y, A.z, nc, off, acc_sum, acc_cnt, acc_max);
        eval_point(A.w, B.x, B.y, nc, off, acc_sum, acc_cnt, acc_max);
        eval_point(B.z, B.w, C.x, nc, off, acc_sum, acc_cnt, acc_max);
        eval_point(C.y, C.z, C.w, nc, off, acc_sum, acc_cnt, acc_max);
    }
    // tail points (npts not a multiple of 4); dead for npts = 2^20
    if (tid0 == 0) {
        for (int i = npts & ~3; i < npts; i++)
            eval_point(pts[3 * i], pts[3 * i + 1], pts[3 * i + 2], nc, off,
                       acc_sum, acc_cnt, acc_max);
    }

    block_reduce(acc_sum, acc_cnt, acc_max, s_sum, s_cnt, s_max);
    if (threadIdx.x == 0) {
        g_psum[blockIdx.x] = acc_sum;
        g_pcnt[blockIdx.x] = acc_cnt;
        g_pmax[blockIdx.x] = acc_max;
    }

    // last-block-finishes final reduction (deterministic fixed-order tree;
    // atomicInc wraps to 0 after the full grid -> safe across graph replays)
    if (threadIdx.x == 0) {
        __threadfence();
        unsigned int t = atomicInc(&g_ticket, (unsigned int)(gridDim.x - 1));
        s_last = (t == (unsigned int)(gridDim.x - 1));
    }
    __syncthreads();
    if (s_last) {
        float fs = 0.0f; int fc = 0; float fm = 0.0f;
        for (int i = threadIdx.x; i < (int)gridDim.x; i += NTHR) {
            fs += g_psum[i];
            fc += g_pcnt[i];
            fm  = fmaxf(fm, g_pmax[i]);
        }
        block_reduce(fs, fc, fm, s_sum, s_cnt, s_max);
        if (threadIdx.x == 0) {
            float loss_in  = (fc > 0) ? (0.001f * fs / (float)fc) : 0.0f;  // W_IN = 0.001
            int   n_out    = npts - fc;
            float loss_out = (n_out > 0) ? fm : 0.0f;                      // W_OUT = 1.0
            out[0] = loss_in + loss_out;
        }
    }
}

extern "C" void kernel_launch(void* const* d_in, const int* in_sizes, int n_in,
                              void* d_out, int out_size)
{
    // inputs: 0=inp_points(N,3) 1=hull_vertices(6,3) 2=hull_tris(8,3,3)
    //         3=face_normals(8,3) 4=face_offsets(8)
    const float* pts     = (const float*)d_in[0];
    const float* normals = (const float*)d_in[3];
    const float* offsets = (const float*)d_in[4];
    int npts = in_sizes[0] / 3;
    palette_loss_kernel<<<NBLK, NTHR>>>(pts, normals, offsets, (float*)d_out, npts);
}

// round 3
// speedup vs baseline: 1.1734x; 1.1734x over previous
#include <cuda_runtime.h>
#include <cuda_bf16.h>

// PaletteBoundLoss: scalar loss over 1M points vs a fixed octahedron hull.
//   loss = W_IN * mean_{inside}(d2 to nearest vertex) + W_OUT * max_{outside}(d2 to surface)
// Octant-folded: q=|p| reduces 8 faces -> 1 plane test, 6 verts -> closed form,
// 8 triangles -> 1 closest-point region cascade vs triangle (e_x,e_y,e_z).
// R3: distance-only cascade — every region's dist^2 in closed form (denominators
// are identically 2 for this triangle), so no divisions, no closest-point coords.

#define NBLK 1036              // 7 * 148 SMs
#define NTHR 256
#define NWARP (NTHR / 32)
#define PB_TOL 1e-8f

__device__ float        g_psum[NBLK];
__device__ int          g_pcnt[NBLK];
__device__ float        g_pmax[NBLK];
__device__ unsigned int g_ticket = 0;

__device__ __forceinline__ void eval_point(float x, float y, float z,
                                           float nc, float off,
                                           float& acc_sum, int& acc_cnt, float& acc_max)
{
    float qx = fabsf(x), qy = fabsf(y), qz = fabsf(z);
    float s = qx + qy + qz;
    bool inside = (s * nc - off) <= PB_TOL;

    // squared distance to nearest hull vertex (+-unit axis points)
    float qq  = fmaf(qx, qx, fmaf(qy, qy, qz * qz));
    float mx3 = fmaxf(qx, fmaxf(qy, qz));
    float e   = qq + 1.0f;
    float d2v = fmaf(-2.0f, mx3, e);

    // Ericson region tests for triangle a=(1,0,0), b=(0,1,0), c=(0,0,1)
    // ab=(-1,1,0), ac=(-1,0,1); ab.ab=2, ab.ac=1, ac.ac=2
    float u  = 1.0f - qx;
    float d1 = u + qy;            // ab . (q-a)
    float d2 = u + qz;            // ac . (q-a)
    float d3 = d1 - 2.0f;         // ab . (q-b)
    float d4 = d2 - 1.0f;         // ac . (q-b)
    float d5 = d1 - 1.0f;         // ab . (q-c)
    float d6 = d2 - 2.0f;         // ac . (q-c)
    float d43 = d4 - d3;          // dot(q-b, c-b);  d43 + d56 == 2 identically
    float d56 = d5 - d6;

    float vc = fmaf(d1, d4, -d3 * d2);
    float vb = fmaf(d5, d2, -d1 * d6);
    float va = fmaf(d3, d6, -d5 * d4);

    // candidate squared distances (closed form, no division)
    float sm1   = s - 1.0f;
    float sq    = sm1 * sm1 * (1.0f / 3.0f);      // interior: plane x+y+z=1
    float sq_a  = fmaf(-2.0f, qx, e);             // |q-a|^2
    float sq_b  = fmaf(-2.0f, qy, e);             // |q-b|^2
    float sq_c  = fmaf(-2.0f, qz, e);             // |q-c|^2
    float sq_bc = fmaf(-0.5f * d43, d43, sq_b);   // |q-b|^2 - d43^2/2
    float sq_ac = fmaf(-0.5f * d2,  d2,  sq_a);   // |q-a|^2 - d2^2/2
    float sq_ab = fmaf(-0.5f * d1,  d1,  sq_a);   // |q-a|^2 - d1^2/2

    // same override priority as reference: interior -> bc -> ac -> ab -> c -> b -> a
    if ((va <= 0.0f) & (d43 >= 0.0f) & (d56 >= 0.0f)) sq = sq_bc;
    if ((vb <= 0.0f) & (d2  >= 0.0f) & (d6  <= 0.0f)) sq = sq_ac;
    if ((vc <= 0.0f) & (d1  >= 0.0f) & (d3  <= 0.0f)) sq = sq_ab;
    if ((d6 >= 0.0f) & (d5 <= d6)) sq = sq_c;
    if ((d3 >= 0.0f) & (d4 <= d3)) sq = sq_b;
    if ((d1 <= 0.0f) & (d2 <= 0.0f)) sq = sq_a;

    acc_sum += inside ? d2v : 0.0f;
    acc_cnt += inside ? 1 : 0;
    acc_max  = fmaxf(acc_max, inside ? 0.0f : sq);
}

// Full block reduction; results valid on thread 0. Uses caller-provided shared bufs.
__device__ __forceinline__ void block_reduce(float& rsum, int& rcnt, float& rmax,
                                             float* s_sum, int* s_cnt, float* s_max)
{
    #pragma unroll
    for (int o = 16; o > 0; o >>= 1) {
        rsum += __shfl_down_sync(0xffffffffu, rsum, o);
        rcnt += __shfl_down_sync(0xffffffffu, rcnt, o);
        rmax  = fmaxf(rmax, __shfl_down_sync(0xffffffffu, rmax, o));
    }
    int lane = threadIdx.x & 31, warp = threadIdx.x >> 5;
    if (lane == 0) { s_sum[warp] = rsum; s_cnt[warp] = rcnt; s_max[warp] = rmax; }
    __syncthreads();
    if (warp == 0) {
        rsum = (lane < NWARP) ? s_sum[lane] : 0.0f;
        rcnt = (lane < NWARP) ? s_cnt[lane] : 0;
        rmax = (lane < NWARP) ? s_max[lane] : 0.0f;
        #pragma unroll
        for (int o = NWARP / 2; o > 0; o >>= 1) {
            rsum += __shfl_down_sync(0xffffffffu, rsum, o);
            rcnt += __shfl_down_sync(0xffffffffu, rcnt, o);
            rmax  = fmaxf(rmax, __shfl_down_sync(0xffffffffu, rmax, o));
        }
    }
    __syncthreads();
}

__global__ void __launch_bounds__(NTHR)
palette_loss_kernel(const float* __restrict__ pts,
                    const float* __restrict__ normals,
                    const float* __restrict__ offsets,
                    float* __restrict__ out, int npts)
{
    __shared__ float s_sum[NWARP];
    __shared__ int   s_cnt[NWARP];
    __shared__ float s_max[NWARP];
    __shared__ bool  s_last;

    const float nc  = fabsf(__ldg(normals));   // |n_x| of face 0 (all components equal magnitude)
    const float off = __ldg(offsets);          // face plane offset (all faces equal)

    float acc_sum = 0.0f; int acc_cnt = 0; float acc_max = 0.0f;

    const int ngroups = npts >> 2;             // 4 points per thread-iteration (3x float4)
    const float4* __restrict__ p4 = reinterpret_cast<const float4*>(pts);
    const int stride = gridDim.x * blockDim.x;
    const int tid0 = blockIdx.x * blockDim.x + threadIdx.x;
    for (int g = tid0; g < ngroups; g += stride) {
        float4 A = __ldg(&p4[3 * g + 0]);
        float4 B = __ldg(&p4[3 * g + 1]);
        float4 C = __ldg(&p4[3 * g + 2]);
        eval_point(A.x, A.y, A.z, nc, off, acc_sum, acc_cnt, acc_max);
        eval_point(A.w, B.x, B.y, nc, off, acc_sum, acc_cnt, acc_max);
        eval_point(B.z, B.w, C.x, nc, off, acc_sum, acc_cnt, acc_max);
        eval_point(C.y, C.z, C.w, nc, off, acc_sum, acc_cnt, acc_max);
    }
    // tail points (npts not a multiple of 4); dead for npts = 2^20
    if (tid0 == 0) {
        for (int i = npts & ~3; i < npts; i++)
            eval_point(pts[3 * i], pts[3 * i + 1], pts[3 * i + 2], nc, off,
                       acc_sum, acc_cnt, acc_max);
    }

    block_reduce(acc_sum, acc_cnt, acc_max, s_sum, s_cnt, s_max);
    if (threadIdx.x == 0) {
        g_psum[blockIdx.x] = acc_sum;
        g_pcnt[blockIdx.x] = acc_cnt;
        g_pmax[blockIdx.x] = acc_max;
    }

    // last-block-finishes final reduction (deterministic fixed-order tree;
    // atomicInc wraps to 0 after the full grid -> safe across graph replays)
    if (threadIdx.x == 0) {
        __threadfence();
        unsigned int t = atomicInc(&g_ticket, (unsigned int)(gridDim.x - 1));
        s_last = (t == (unsigned int)(gridDim.x - 1));
    }
    __syncthreads();
    if (s_last) {
        float fs = 0.0f; int fc = 0; float fm = 0.0f;
        for (int i = threadIdx.x; i < (int)gridDim.x; i += NTHR) {
            fs += g_psum[i];
            fc += g_pcnt[i];
            fm  = fmaxf(fm, g_pmax[i]);
        }
        block_reduce(fs, fc, fm, s_sum, s_cnt, s_max);
        if (threadIdx.x == 0) {
            float loss_in  = (fc > 0) ? (0.001f * fs / (float)fc) : 0.0f;  // W_IN = 0.001
            int   n_out    = npts - fc;
            float loss_out = (n_out > 0) ? fm : 0.0f;                      // W_OUT = 1.0
            out[0] = loss_in + loss_out;
        }
    }
}

extern "C" void kernel_launch(void* const* d_in, const int* in_sizes, int n_in,
                              void* d_out, int out_size)
{
    // inputs: 0=inp_points(N,3) 1=hull_vertices(6,3) 2=hull_tris(8,3,3)
    //         3=face_normals(8,3) 4=face_offsets(8)
    const float* pts     = (const float*)d_in[0];
    const float* normals = (const float*)d_in[3];
    const float* offsets = (const float*)d_in[4];
    int npts = in_sizes[0] / 3;
    palette_loss_kernel<<<NBLK, NTHR>>>(pts, normals, offsets, (float*)d_out, npts);
}

// round 4
// speedup vs baseline: 1.2492x; 1.0646x over previous
#include <cuda_runtime.h>
#include <cuda_bf16.h>

// PaletteBoundLoss: scalar loss over 1M points vs a fixed octahedron hull.
//   loss = W_IN * mean_{inside}(d2 to nearest vertex) + W_OUT * max_{outside}(d2 to surface)
// Octant fold: q=|p|. Inside test: s=qx+qy+qz vs plane threshold.
// Surface distance = distance from q to the probability simplex (triangle
// (e_x,e_y,e_z)) via closed-form simplex projection (sort-based, 3 cases):
//   k=3: sq = 3*((s-1)/3)^2        if min(q) > (s-1)/3
//   k=2: sq = 2*t2^2 + mn^2,  t2=(s-mn-1)/2   if mid(q) > t2
//   k=1: sq = qq - 2*max(q) + 1   (== nearest-vertex distance d2v)

#define NBLK 518               // 3.5 * 148 SMs, single wave, 2 groups/thread
#define NTHR 256
#define NWARP (NTHR / 32)
#define PB_TOL 1e-8f

__device__ float        g_psum[NBLK];
__device__ int          g_pcnt[NBLK];
__device__ float        g_pmax[NBLK];
__device__ unsigned int g_ticket = 0;

__device__ __forceinline__ void eval_point(float x, float y, float z,
                                           float thr,
                                           float& acc_sum, int& acc_cnt, float& acc_max)
{
    float qx = fabsf(x), qy = fabsf(y), qz = fabsf(z);
    float s  = qx + qy + qz;
    bool inside = s <= thr;

    float qq = fmaf(qx, qx, fmaf(qy, qy, qz * qz));
    float mx = fmaxf(qx, fmaxf(qy, qz));
    float mn = fminf(qx, fminf(qy, qz));
    float md = (s - mx) - mn;

    float d2v = fmaf(-2.0f, mx, qq + 1.0f);       // nearest-vertex dist^2 (also k=1 case)

    float t3  = (s - 1.0f) * (1.0f / 3.0f);
    float t2  = ((s - mn) - 1.0f) * 0.5f;
    float sq3 = 3.0f * t3 * t3;
    float sq2 = fmaf(2.0f * t2, t2, mn * mn);

    float sq = (md > t2) ? sq2 : d2v;             // k=2 else k=1
    sq       = (mn > t3) ? sq3 : sq;              // k=3 wins if interior projection valid

    acc_sum += inside ? d2v : 0.0f;
    acc_cnt += inside ? 1 : 0;
    acc_max  = fmaxf(acc_max, inside ? 0.0f : sq);
}

// Full block reduction; results valid on thread 0. Uses caller-provided shared bufs.
__device__ __forceinline__ void block_reduce(float& rsum, int& rcnt, float& rmax,
                                             float* s_sum, int* s_cnt, float* s_max)
{
    #pragma unroll
    for (int o = 16; o > 0; o >>= 1) {
        rsum += __shfl_down_sync(0xffffffffu, rsum, o);
        rcnt += __shfl_down_sync(0xffffffffu, rcnt, o);
        rmax  = fmaxf(rmax, __shfl_down_sync(0xffffffffu, rmax, o));
    }
    int lane = threadIdx.x & 31, warp = threadIdx.x >> 5;
    if (lane == 0) { s_sum[warp] = rsum; s_cnt[warp] = rcnt; s_max[warp] = rmax; }
    __syncthreads();
    if (warp == 0) {
        rsum = (lane < NWARP) ? s_sum[lane] : 0.0f;
        rcnt = (lane < NWARP) ? s_cnt[lane] : 0;
        rmax = (lane < NWARP) ? s_max[lane] : 0.0f;
        #pragma unroll
        for (int o = NWARP / 2; o > 0; o >>= 1) {
            rsum += __shfl_down_sync(0xffffffffu, rsum, o);
            rcnt += __shfl_down_sync(0xffffffffu, rcnt, o);
            rmax  = fmaxf(rmax, __shfl_down_sync(0xffffffffu, rmax, o));
        }
    }
    __syncthreads();
}

__global__ void __launch_bounds__(NTHR)
palette_loss_kernel(const float* __restrict__ pts,
                    const float* __restrict__ normals,
                    const float* __restrict__ offsets,
                    float* __restrict__ out, int npts)
{
    __shared__ float s_sum[NWARP];
    __shared__ int   s_cnt[NWARP];
    __shared__ float s_max[NWARP];
    __shared__ bool  s_last;

    const float nc  = fabsf(__ldg(normals));            // |n_x| (all comps equal magnitude)
    const float off = __ldg(offsets);                    // plane offset (all faces equal)
    const float thr = (off + PB_TOL) * __frcp_rn(nc);   // inside <=> s <= thr

    float acc_sum = 0.0f; int acc_cnt = 0; float acc_max = 0.0f;

    const int ngroups = npts >> 2;             // 4 points per group (3x float4)
    const float4* __restrict__ p4 = reinterpret_cast<const float4*>(pts);
    const int stride = gridDim.x * blockDim.x;
    const int tid0 = blockIdx.x * blockDim.x + threadIdx.x;
    for (int g = tid0; g < ngroups; g += stride) {
        float4 A = __ldg(&p4[3 * g + 0]);
        float4 B = __ldg(&p4[3 * g + 1]);
        float4 C = __ldg(&p4[3 * g + 2]);
        eval_point(A.x, A.y, A.z, thr, acc_sum, acc_cnt, acc_max);
        eval_point(A.w, B.x, B.y, thr, acc_sum, acc_cnt, acc_max);
        eval_point(B.z, B.w, C.x, thr, acc_sum, acc_cnt, acc_max);
        eval_point(C.y, C.z, C.w, thr, acc_sum, acc_cnt, acc_max);
    }
    // tail points (npts not a multiple of 4); dead for npts = 2^20
    if (tid0 == 0) {
        for (int i = npts & ~3; i < npts; i++)
            eval_point(pts[3 * i], pts[3 * i + 1], pts[3 * i + 2], thr,
                       acc_sum, acc_cnt, acc_max);
    }

    block_reduce(acc_sum, acc_cnt, acc_max, s_sum, s_cnt, s_max);
    if (threadIdx.x == 0) {
        g_psum[blockIdx.x] = acc_sum;
        g_pcnt[blockIdx.x] = acc_cnt;
        g_pmax[blockIdx.x] = acc_max;
    }

    // last-block-finishes final reduction (deterministic fixed-order tree;
    // atomicInc wraps to 0 after the full grid -> safe across graph replays)
    if (threadIdx.x == 0) {
        __threadfence();
        unsigned int t = atomicInc(&g_ticket, (unsigned int)(gridDim.x - 1));
        s_last = (t == (unsigned int)(gridDim.x - 1));
    }
    __syncthreads();
    if (s_last) {
        float fs = 0.0f; int fc = 0; float fm = 0.0f;
        for (int i = threadIdx.x; i < (int)gridDim.x; i += NTHR) {
            fs += g_psum[i];
            fc += g_pcnt[i];
            fm  = fmaxf(fm, g_pmax[i]);
        }
        block_reduce(fs, fc, fm, s_sum, s_cnt, s_max);
        if (threadIdx.x == 0) {
            float loss_in  = (fc > 0) ? (0.001f * fs / (float)fc) : 0.0f;  // W_IN = 0.001
            int   n_out    = npts - fc;
            float loss_out = (n_out > 0) ? fm : 0.0f;                      // W_OUT = 1.0
            out[0] = loss_in + loss_out;
        }
    }
}

extern "C" void kernel_launch(void* const* d_in, const int* in_sizes, int n_in,
                              void* d_out, int out_size)
{
    // inputs: 0=inp_points(N,3) 1=hull_vertices(6,3) 2=hull_tris(8,3,3)
    //         3=face_normals(8,3) 4=face_offsets(8)
    const float* pts     = (const float*)d_in[0];
    const float* normals = (const float*)d_in[3];
    const float* offsets = (const float*)d_in[4];
    int npts = in_sizes[0] / 3;
    palette_loss_kernel<<<NBLK, NTHR>>>(pts, normals, offsets, (float*)d_out, npts);
}

// round 5
// speedup vs baseline: 1.2648x; 1.0125x over previous
#include <cuda_runtime.h>
#include <cuda_bf16.h>

// PaletteBoundLoss: scalar loss over 1M points vs a fixed octahedron hull.
//   loss = W_IN * mean_{inside}(d2 to nearest vertex) + W_OUT * max_{outside}(d2 to surface)
// Octant fold: q=|p|. Inside test: s=qx+qy+qz vs plane threshold.
// Surface distance = distance from q to the probability simplex (triangle
// (e_x,e_y,e_z)) via closed-form simplex projection (sort-based, 3 cases):
//   k=3: sq = 3*((s-1)/3)^2        if min(q) > (s-1)/3
//   k=2: sq = 2*t2^2 + mn^2,  t2=(s-mn-1)/2   if mid(q) > t2
//   k=1: sq = qq - 2*max(q) + 1   (== nearest-vertex distance d2v)

#define NBLK 518               // 3.5 * 148 SMs, single wave, 2 groups/thread
#define NTHR 256
#define NWARP (NTHR / 32)
#define PB_TOL 1e-8f

__device__ float        g_psum[NBLK];
__device__ int          g_pcnt[NBLK];
__device__ float        g_pmax[NBLK];
__device__ unsigned int g_ticket = 0;

__device__ __forceinline__ void eval_point(float x, float y, float z,
                                           float thr,
                                           float& acc_sum, int& acc_cnt, float& acc_max)
{
    float qx = fabsf(x), qy = fabsf(y), qz = fabsf(z);
    float s  = qx + qy + qz;
    bool inside = s <= thr;

    float qq = fmaf(qx, qx, fmaf(qy, qy, qz * qz));
    float mx = fmaxf(qx, fmaxf(qy, qz));
    float mn = fminf(qx, fminf(qy, qz));
    float md = (s - mx) - mn;

    float d2v = fmaf(-2.0f, mx, qq + 1.0f);       // nearest-vertex dist^2 (also k=1 case)

    float t3  = (s - 1.0f) * (1.0f / 3.0f);
    float t2  = ((s - mn) - 1.0f) * 0.5f;
    float sq3 = 3.0f * t3 * t3;
    float sq2 = fmaf(2.0f * t2, t2, mn * mn);

    float sq = (md > t2) ? sq2 : d2v;             // k=2 else k=1
    sq       = (mn > t3) ? sq3 : sq;              // k=3 wins if interior projection valid

    acc_sum += inside ? d2v : 0.0f;
    acc_cnt += inside ? 1 : 0;
    acc_max  = fmaxf(acc_max, inside ? 0.0f : sq);
}

// Full block reduction; results valid on thread 0. Uses caller-provided shared bufs.
__device__ __forceinline__ void block_reduce(float& rsum, int& rcnt, float& rmax,
                                             float* s_sum, int* s_cnt, float* s_max)
{
    #pragma unroll
    for (int o = 16; o > 0; o >>= 1) {
        rsum += __shfl_down_sync(0xffffffffu, rsum, o);
        rcnt += __shfl_down_sync(0xffffffffu, rcnt, o);
        rmax  = fmaxf(rmax, __shfl_down_sync(0xffffffffu, rmax, o));
    }
    int lane = threadIdx.x & 31, warp = threadIdx.x >> 5;
    if (lane == 0) { s_sum[warp] = rsum; s_cnt[warp] = rcnt; s_max[warp] = rmax; }
    __syncthreads();
    if (warp == 0) {
        rsum = (lane < NWARP) ? s_sum[lane] : 0.0f;
        rcnt = (lane < NWARP) ? s_cnt[lane] : 0;
        rmax = (lane < NWARP) ? s_max[lane] : 0.0f;
        #pragma unroll
        for (int o = NWARP / 2; o > 0; o >>= 1) {
            rsum += __shfl_down_sync(0xffffffffu, rsum, o);
            rcnt += __shfl_down_sync(0xffffffffu, rcnt, o);
            rmax  = fmaxf(rmax, __shfl_down_sync(0xffffffffu, rmax, o));
        }
    }
    __syncthreads();
}

__global__ void __launch_bounds__(NTHR)
palette_loss_kernel(const float* __restrict__ pts,
                    const float* __restrict__ normals,
                    const float* __restrict__ offsets,
                    float* __restrict__ out, int npts)
{
    __shared__ float s_sum[NWARP];
    __shared__ int   s_cnt[NWARP];
    __shared__ float s_max[NWARP];
    __shared__ bool  s_last;

    const float nc  = fabsf(__ldg(normals));            // |n_x| (all comps equal magnitude)
    const float off = __ldg(offsets);                    // plane offset (all faces equal)
    const float thr = (off + PB_TOL) * __frcp_rn(nc);   // inside <=> s <= thr

    float acc_sum = 0.0f; int acc_cnt = 0; float acc_max = 0.0f;

    const int ngroups = npts >> 2;             // 4 points per group (3x float4)
    const float4* __restrict__ p4 = reinterpret_cast<const float4*>(pts);
    const int stride = gridDim.x * blockDim.x;
    const int tid0 = blockIdx.x * blockDim.x + threadIdx.x;
    for (int g = tid0; g < ngroups; g += stride) {
        float4 A = __ldg(&p4[3 * g + 0]);
        float4 B = __ldg(&p4[3 * g + 1]);
        float4 C = __ldg(&p4[3 * g + 2]);
        eval_point(A.x, A.y, A.z, thr, acc_sum, acc_cnt, acc_max);
        eval_point(A.w, B.x, B.y, thr, acc_sum, acc_cnt, acc_max);
        eval_point(B.z, B.w, C.x, thr, acc_sum, acc_cnt, acc_max);
        eval_point(C.y, C.z, C.w, thr, acc_sum, acc_cnt, acc_max);
    }
    // tail points (npts not a multiple of 4); dead for npts = 2^20
    if (tid0 == 0) {
        for (int i = npts & ~3; i < npts; i++)
            eval_point(pts[3 * i], pts[3 * i + 1], pts[3 * i + 2], thr,
                       acc_sum, acc_cnt, acc_max);
    }

    block_reduce(acc_sum, acc_cnt, acc_max, s_sum, s_cnt, s_max);
    if (threadIdx.x == 0) {
        g_psum[blockIdx.x] = acc_sum;
        g_pcnt[blockIdx.x] = acc_cnt;
        g_pmax[blockIdx.x] = acc_max;
    }

    // last-block-finishes final reduction (deterministic fixed-order tree;
    // atomicInc wraps to 0 after the full grid -> safe across graph replays)
    if (threadIdx.x == 0) {
        __threadfence();
        unsigned int t = atomicInc(&g_ticket, (unsigned int)(gridDim.x - 1));
        s_last = (t == (unsigned int)(gridDim.x - 1));
    }
    __syncthreads();
    if (s_last) {
        float fs = 0.0f; int fc = 0; float fm = 0.0f;
        for (int i = threadIdx.x; i < (int)gridDim.x; i += NTHR) {
            fs += g_psum[i];
            fc += g_pcnt[i];
            fm  = fmaxf(fm, g_pmax[i]);
        }
        block_reduce(fs, fc, fm, s_sum, s_cnt, s_max);
        if (threadIdx.x == 0) {
            float loss_in  = (fc > 0) ? (0.001f * fs / (float)fc) : 0.0f;  // W_IN = 0.001
            int   n_out    = npts - fc;
            float loss_out = (n_out > 0) ? fm : 0.0f;                      // W_OUT = 1.0
            out[0] = loss_in + loss_out;
        }
    }
}

extern "C" void kernel_launch(void* const* d_in, const int* in_sizes, int n_in,
                              void* d_out, int out_size)
{
    // inputs: 0=inp_points(N,3) 1=hull_vertices(6,3) 2=hull_tris(8,3,3)
    //         3=face_normals(8,3) 4=face_offsets(8)
    const float* pts     = (const float*)d_in[0];
    const float* normals = (const float*)d_in[3];
    const float* offsets = (const float*)d_in[4];
    int npts = in_sizes[0] / 3;
    palette_loss_kernel<<<NBLK, NTHR>>>(pts, normals, offsets, (float*)d_out, npts);
}